// round 10
// baseline (speedup 1.0000x reference)
#include <cuda_runtime.h>

#define NS   48000
#define NIN  400
#define NSEG 401      // head(60) + 399 interior(120) + tail(60)
#define NB   16
#define NM   64
#define NROWS (NB*NM)
#define NTILE (NSEG*NB)
#define BPSM 28       // co-resident blocks per SM (regs capped at 36)

// Scratch (allocation-free)
__device__ float2 g_Bp[(size_t)NROWS * NSEG];  // per-(row,seg) phase base {radians, turns}
__device__ double g_FT[NSEG];                  // per-segment frac totals (for scan)
__device__ float4 g_F1q[NSEG * 30];            // frac-cumsum table (float4-packed, 120/seg)

// Software grid barrier (paired-flag: completer of barrier i resets flag i^1
// before raising flag i, so device state is valid for every graph replay).
// Deadlock-free: all blocks are co-resident by construction, and flag i can
// only be reset by barrier (i^1)'s completer, which requires every block to
// have already exited barrier i's poll.
__device__ int g_cnt[2];
__device__ int g_flg[2];

__device__ __forceinline__ void grid_bar(int idx) {
    __threadfence();
    __syncthreads();
    if (threadIdx.x == 0) {
        int t = atomicAdd(&g_cnt[idx], 1);
        if (t == (int)gridDim.x - 1) {
            g_cnt[idx] = 0;
            *(volatile int*)&g_flg[idx ^ 1] = 0;
            __threadfence();
            *(volatile int*)&g_flg[idx] = 1;
        } else {
            while (*(volatile int*)&g_flg[idx] != 1) { __nanosleep(20); }
        }
    }
    __syncthreads();
    __threadfence();
}

// Exact replica of the reference's fp32 position/frac computation.
__device__ __forceinline__ float ref_frac(int j) {
    const float SCALE = 400.0f / 48000.0f;   // fl32(1/120)
    float pos = __fsub_rn(__fmul_rn(__fadd_rn((float)j, 0.5f), SCALE), 0.5f);
    pos = fminf(fmaxf(pos, 0.0f), 399.0f);
    float fi = floorf(pos);
    return __fsub_rn(pos, fi);               // exact (Sterbenz)
}

__global__ void __launch_bounds__(64, BPSM)
fused_kernel(const float* __restrict__ params, float* __restrict__ out) {
    int tid  = threadIdx.x;
    int lane = tid & 31, wp = tid >> 5;
    int nb   = gridDim.x;

    __shared__ float4 md0[64];   // {base_rad, f0_rad, dF_rad, a0}
    __shared__ float4 md1[64];   // {base_trn, f0_trn, dF_trn, da}
    __shared__ double sW[2];

    // ---------------- Phase A: frac-cumsum table, one warp per segment ------
    if (blockIdx.x <= 200) {
        int s = blockIdx.x * 2 + wp;
        if (s < NSEG) {
            int start = (s == 0) ? 0 : 60 + (s - 1) * 120;
            int m0 = lane * 4;
            double s0 = (double)ref_frac(start + m0);
            double s1 = s0 + (double)ref_frac(start + m0 + 1);
            double s2 = s1 + (double)ref_frac(start + m0 + 2);
            double s3 = s2 + (double)ref_frac(start + m0 + 3);
            double T = s3, inc = T;
            #pragma unroll
            for (int off = 1; off < 32; off <<= 1) {
                double n = __shfl_up_sync(0xFFFFFFFFu, inc, off);
                if (lane >= off) inc += n;
            }
            double base = inc - T;            // exclusive prefix of lane totals
            if (m0 < 120)
                g_F1q[s * 30 + lane] = make_float4((float)(base + s0), (float)(base + s1),
                                                   (float)(base + s2), (float)(base + s3));
            if (lane == 30) g_FT[s] = base;   // sum over samples 0..119
        }
    }
    grid_bar(0);

    // ---------------- Phase B: per-row fp64 scan (block = row) --------------
    if (blockIdx.x < NROWS) {
        int r = blockIdx.x;
        int b = r >> 6, mode = r & 63;
        const float* F = params + (size_t)(b * 192 + mode) * 400;  // freqs
        const float* P = F + 128 * 400;                            // phase
        float p0 = P[0];

        double loc[7];
        double run = 0.0;
        #pragma unroll
        for (int i = 0; i < 7; i++) {
            int idx = tid * 7 + i;
            double v = 0.0;
            if (idx == 0) {
                v = 60.0 * (double)F[0];
            } else if (idx <= 399) {
                double f0 = F[idx - 1], f1 = F[idx];
                v = 120.0 * f0 + (f1 - f0) * g_FT[idx];
            }
            run += v;
            loc[i] = run;                     // local inclusive
        }
        double T = run, inc = T;
        #pragma unroll
        for (int off = 1; off < 32; off <<= 1) {
            double n = __shfl_up_sync(0xFFFFFFFFu, inc, off);
            if (lane >= off) inc += n;
        }
        if (lane == 31) sW[wp] = inc;
        __syncthreads();
        double tbase = (inc - T) + ((wp == 1) ? sW[0] : 0.0);

        #pragma unroll
        for (int i = 0; i < 7; i++) {
            int idx = tid * 7 + i;
            if (idx <= 400) {
                double excl = tbase + (i ? loc[i - 1] : 0.0);
                double tot  = excl + (double)p0;
                double tt   = tot * 0.15915494309189535;   // turns
                double kk   = rint(tt);
                double ft   = tt - kk;                     // [-0.5, 0.5] turns
                g_Bp[(size_t)r * NSEG + idx] =
                    make_float2((float)(ft * 6.283185307179586), (float)ft);
            }
        }
    }
    grid_bar(1);

    // ---------------- Phase C: synthesis tiles (grid-stride) ----------------
    const float MAGIC  = 12582912.0f;       // 1.5 * 2^23
    const float TWOPI  = 6.2831853f;
    const float C11 = -2.3889859e-08f;
    const float C9  =  2.7525562e-06f;
    const float C7  = -0.00019840874f;
    const float C5  =  0.0083333310f;
    const float C3  = -0.16666667f;
    const float INV2PI_F = 0.15915494f;
    const float* F1 = (const float*)g_F1q;

    for (int tile = blockIdx.x; tile < NTILE; tile += nb) {
        int s = tile % NSEG, b = tile / NSEG;

        {   // per-tile mode constants (64 threads == 64 modes)
            int mode = tid;
            const float* F = params + (size_t)(b * 192 + mode) * 400;
            const float* A = F + 64 * 400;
            int i  = (s == 0) ? 0 : ((s <= 399) ? s - 1 : 399);
            int i1 = min(i + 1, 399);
            float f0 = F[i];
            float dw = F[i1] - f0;
            float a0 = A[i];
            float da = A[i1] - a0;
            float2 bp = g_Bp[(size_t)(b * 64 + mode) * NSEG + s];
            md0[mode] = make_float4(bp.x, f0, dw, a0);
            md1[mode] = make_float4(bp.y, f0 * INV2PI_F, dw * INV2PI_F, da);
        }
        __syncthreads();

        int m = tid;
        if (m < 60) {
            bool interior = (s != 0 && s != 400);
            int start = (s == 0) ? 0 : 60 + (s - 1) * 120;
            int j0 = start + m;
            int j1 = start + m + 60;

            float t1a = (float)(m + 1),  t1b = (float)(m + 61);
            float F1a = F1[s * 120 + m], F1b = F1[s * 120 + m + 60];
            float fra = ref_frac(j0);
            float frb = interior ? ref_frac(j1) : 0.0f;

            float acc_a = 0.0f, acc_b = 0.0f;
            #pragma unroll
            for (int k = 0; k < 64; k++) {
                // 7-of-32 poly pattern: {0,5,10,15,20,25,30} per 32
                bool poly = ((k & 31) % 5 == 0) && ((k & 31) != 31);
                if (poly) {
                    // fma-pipe path: turns + magic reduce + deg-11 odd minimax
                    float4 q = md1[k];
                    float a0k = md0[k].w, dak = q.w;
                    float ph = fmaf(t1a, q.y, q.x); ph = fmaf(F1a, q.z, ph);
                    float kr = (ph + MAGIC) - MAGIC;
                    float r  = (ph - kr) * TWOPI;
                    float x2 = r * r;
                    float p  = fmaf(C11, x2, C9);
                    p = fmaf(p, x2, C7); p = fmaf(p, x2, C5);
                    p = fmaf(p, x2, C3); p = fmaf(p, x2, 1.0f);
                    float aa = fmaf(dak, fra, a0k);
                    acc_a = fmaf(aa * r, p, acc_a);
                    float phb = fmaf(t1b, q.y, q.x); phb = fmaf(F1b, q.z, phb);
                    float krb = (phb + MAGIC) - MAGIC;
                    float rb  = (phb - krb) * TWOPI;
                    float xb2 = rb * rb;
                    float pb  = fmaf(C11, xb2, C9);
                    pb = fmaf(pb, xb2, C7); pb = fmaf(pb, xb2, C5);
                    pb = fmaf(pb, xb2, C3); pb = fmaf(pb, xb2, 1.0f);
                    float ab = fmaf(dak, frb, a0k);
                    acc_b = fmaf(ab * rb, pb, acc_b);
                } else {
                    // MUFU path
                    float4 q = md0[k];
                    float dak = md1[k].w;
                    float ph  = fmaf(t1a, q.y, q.x); ph  = fmaf(F1a, q.z, ph);
                    float phb = fmaf(t1b, q.y, q.x); phb = fmaf(F1b, q.z, phb);
                    float aa = fmaf(dak, fra, q.w);
                    float ab = fmaf(dak, frb, q.w);
                    acc_a = fmaf(aa, __sinf(ph),  acc_a);
                    acc_b = fmaf(ab, __sinf(phb), acc_b);
                }
            }
            out[(size_t)b * NS + j0] = acc_a;
            if (interior) out[(size_t)b * NS + j1] = acc_b;
        }
        __syncthreads();   // md reused next tile
    }
}

extern "C" void kernel_launch(void* const* d_in, const int* in_sizes, int n_in,
                              void* d_out, int out_size) {
    const float* params = (const float*)d_in[0];
    float* out = (float*)d_out;
    int nsm = 148;
    cudaDeviceGetAttribute(&nsm, cudaDevAttrMultiProcessorCount, 0);
    int nblocks = nsm * BPSM;   // co-resident by construction (launch_bounds 64,28)
    fused_kernel<<<nblocks, 64>>>(params, out);
}

// round 12
// speedup vs baseline: 1.4677x; 1.4677x over previous
#include <cuda_runtime.h>

#define NS   48000
#define NIN  400
#define NSEG 401      // head(60) + 399 interior(120) + tail(60)
#define NB   16
#define NM   64
#define NROWS (NB*NM)
#define PREP_BLOCKS 1024

// Scratch (allocation-free)
__device__ float2 g_Bp[(size_t)NROWS * NSEG];  // per-(row,seg) phase base {radians, turns}
__device__ double g_FT[NSEG];                  // per-segment frac totals (for scan)
__device__ float4 g_F1q[NSEG * 30];            // frac-cumsum table (float4-packed, 120/seg)

// Software grid barrier (paired-flag scheme: completer resets the other flag,
// so state is valid again for every graph replay).
__device__ int g_cnt[2];
__device__ int g_flg[2];

__device__ __forceinline__ void grid_bar(int idx, int nblocks) {
    __threadfence();
    __syncthreads();
    if (threadIdx.x == 0) {
        int t = atomicAdd(&g_cnt[idx], 1);
        if (t == nblocks - 1) {
            g_cnt[idx] = 0;
            *(volatile int*)&g_flg[idx ^ 1] = 0;
            __threadfence();
            *(volatile int*)&g_flg[idx] = 1;
        } else {
            while (*(volatile int*)&g_flg[idx] != 1) { __nanosleep(20); }
        }
    }
    __syncthreads();
    __threadfence();
}

// Exact replica of the reference's fp32 position/frac computation.
__device__ __forceinline__ float ref_frac(int j) {
    const float SCALE = 400.0f / 48000.0f;   // fl32(1/120)
    float pos = __fsub_rn(__fmul_rn(__fadd_rn((float)j, 0.5f), SCALE), 0.5f);
    pos = fminf(fmaxf(pos, 0.0f), 399.0f);
    float fi = floorf(pos);
    return __fsub_rn(pos, fi);               // exact (Sterbenz)
}

// Prep kernel: Phase A (frac table, warp-per-segment) -> grid barrier ->
// Phase B (block-per-row fp64 scan + mod-2pi base reduction).
__global__ void __launch_bounds__(128, 8)
prep_kernel(const float* __restrict__ params) {
    int tid  = threadIdx.x;
    int lane = tid & 31, wp = tid >> 5;

    // ---- Phase A: one warp per segment (blocks 0..100 cover 404 >= 401) ----
    {
        int s = blockIdx.x * 4 + wp;
        if (blockIdx.x <= 100 && s < NSEG) {
            int start = (s == 0) ? 0 : 60 + (s - 1) * 120;
            int m0 = lane * 4;
            double s0 = (double)ref_frac(start + m0);
            double s1 = s0 + (double)ref_frac(start + m0 + 1);
            double s2 = s1 + (double)ref_frac(start + m0 + 2);
            double s3 = s2 + (double)ref_frac(start + m0 + 3);
            double T = s3, inc = T;
            #pragma unroll
            for (int off = 1; off < 32; off <<= 1) {
                double n = __shfl_up_sync(0xFFFFFFFFu, inc, off);
                if (lane >= off) inc += n;
            }
            double base = inc - T;            // exclusive prefix of lane totals
            if (m0 < 120)
                g_F1q[s * 30 + lane] = make_float4((float)(base + s0), (float)(base + s1),
                                                   (float)(base + s2), (float)(base + s3));
            if (lane == 30) g_FT[s] = base;   // sum over samples 0..119
        }
    }
    grid_bar(0, PREP_BLOCKS);

    // ---- Phase B: block = row; 128 threads x 4 contiguous values ----------
    {
        int r = blockIdx.x;                 // 0..1023
        int b = r >> 6, mode = r & 63;
        const float* F = params + (size_t)(b * 192 + mode) * 400;  // freqs
        const float* P = F + 128 * 400;                            // phase
        float p0 = P[0];

        double loc[4];
        double run = 0.0;
        #pragma unroll
        for (int i = 0; i < 4; i++) {
            int idx = tid * 4 + i;
            double v = 0.0;
            if (idx == 0) {
                v = 60.0 * (double)F[0];
            } else if (idx <= 399) {
                double f0 = F[idx - 1], f1 = F[idx];
                v = 120.0 * f0 + (f1 - f0) * g_FT[idx];
            }
            run += v;
            loc[i] = run;                     // local inclusive
        }
        // warp scan of thread totals
        double T = run, inc = T;
        #pragma unroll
        for (int off = 1; off < 32; off <<= 1) {
            double n = __shfl_up_sync(0xFFFFFFFFu, inc, off);
            if (lane >= off) inc += n;
        }
        __shared__ double sW[4];
        if (lane == 31) sW[wp] = inc;
        __syncthreads();
        double wbase = 0.0;
        #pragma unroll
        for (int i = 0; i < 3; i++)
            if (i < wp) wbase += sW[i];
        double tbase = wbase + (inc - T);

        #pragma unroll
        for (int i = 0; i < 4; i++) {
            int idx = tid * 4 + i;
            if (idx <= 400) {
                double excl = tbase + (i ? loc[i - 1] : 0.0);
                double tot  = excl + (double)p0;
                double tt   = tot * 0.15915494309189535;   // turns
                double kk   = rint(tt);
                double ft   = tt - kk;                     // [-0.5, 0.5] turns
                g_Bp[(size_t)r * NSEG + idx] =
                    make_float2((float)(ft * 6.283185307179586), (float)ft);
            }
        }
    }
}

// Synthesis: block=(segment s, batch b), 64 threads, 2 samples/thread.
// Hybrid sin at the refined pipe balance: 6 of every 32 modes via fma-pipe
// polynomial (turns phase, magic-rint reduce, deg-9 odd minimax), rest MUFU.
__global__ void __launch_bounds__(64) synth_kernel(const float* __restrict__ params,
                                                   float* __restrict__ out) {
    int s = blockIdx.x, b = blockIdx.y;
    __shared__ float4 md0[64];   // {base_rad, f0_rad, dF_rad, a0}
    __shared__ float4 md1[64];   // {base_trn, f0_trn, dF_trn, da}
    int tid = threadIdx.x;

    {
        int mode = tid;          // 64 threads == 64 modes
        const float* F = params + (size_t)(b * 192 + mode) * 400;
        const float* A = F + 64 * 400;      // channel 1 = amps
        int i  = (s == 0) ? 0 : ((s <= 399) ? s - 1 : 399);
        int i1 = min(i + 1, 399);
        float f0 = F[i];
        float dw = F[i1] - f0;
        float a0 = A[i];
        float da = A[i1] - a0;
        float2 bp = g_Bp[(size_t)(b * 64 + mode) * NSEG + s];
        const float INV2PI_F = 0.15915494f;
        md0[mode] = make_float4(bp.x, f0, dw, a0);
        md1[mode] = make_float4(bp.y, f0 * INV2PI_F, dw * INV2PI_F, da);
    }
    __syncthreads();

    int m = tid;
    if (m >= 60) return;                    // 60 threads x 2 samples = 120
    bool interior = (s != 0 && s != 400);
    int start = (s == 0) ? 0 : 60 + (s - 1) * 120;
    int j0 = start + m;
    int j1 = start + m + 60;

    const float* F1 = (const float*)g_F1q;
    float t1a = (float)(m + 1),  t1b = (float)(m + 61);
    float F1a = F1[s * 120 + m], F1b = F1[s * 120 + m + 60];
    float fra = ref_frac(j0);
    float frb = interior ? ref_frac(j1) : 0.0f;

    const float MAGIC  = 12582912.0f;       // 1.5 * 2^23
    const float TWOPI  = 6.2831853f;
    const float C9  =  2.7525562e-06f;
    const float C7  = -0.00019840874f;
    const float C5  =  0.0083333310f;
    const float C3  = -0.16666667f;

    float acc_a = 0.0f, acc_b = 0.0f;
#pragma unroll
    for (int k = 0; k < 64; k++) {
        // 6-of-32 poly pattern (x = 0.1875, near optimum 0.174)
        int k32 = k & 31;
        bool poly = (k32 == 0) || (k32 == 5) || (k32 == 11) ||
                    (k32 == 16) || (k32 == 21) || (k32 == 27);
        if (poly) {
            // fma-pipe path: turns + magic reduce + deg-9 odd minimax
            float4 q = md1[k];
            float a0k = md0[k].w, dak = q.w;
            float ph = fmaf(t1a, q.y, q.x); ph = fmaf(F1a, q.z, ph);
            float kr = (ph + MAGIC) - MAGIC;        // rint(ph) in turns
            float r  = (ph - kr) * TWOPI;           // [-pi, pi] radians
            float x2 = r * r;
            float p  = fmaf(C9, x2, C7);
            p = fmaf(p, x2, C5);
            p = fmaf(p, x2, C3); p = fmaf(p, x2, 1.0f);
            float aa = fmaf(dak, fra, a0k);
            acc_a = fmaf(aa * r, p, acc_a);
            float phb = fmaf(t1b, q.y, q.x); phb = fmaf(F1b, q.z, phb);
            float krb = (phb + MAGIC) - MAGIC;
            float rb  = (phb - krb) * TWOPI;
            float xb2 = rb * rb;
            float pb  = fmaf(C9, xb2, C7);
            pb = fmaf(pb, xb2, C5);
            pb = fmaf(pb, xb2, C3); pb = fmaf(pb, xb2, 1.0f);
            float ab = fmaf(dak, frb, a0k);
            acc_b = fmaf(ab * rb, pb, acc_b);
        } else {
            // MUFU path
            float4 q = md0[k];
            float dak = md1[k].w;
            float ph  = fmaf(t1a, q.y, q.x); ph  = fmaf(F1a, q.z, ph);
            float phb = fmaf(t1b, q.y, q.x); phb = fmaf(F1b, q.z, phb);
            float aa = fmaf(dak, fra, q.w);
            float ab = fmaf(dak, frb, q.w);
            acc_a = fmaf(aa, __sinf(ph),  acc_a);
            acc_b = fmaf(ab, __sinf(phb), acc_b);
        }
    }

    out[(size_t)b * NS + j0] = acc_a;
    if (interior) out[(size_t)b * NS + j1] = acc_b;
}

extern "C" void kernel_launch(void* const* d_in, const int* in_sizes, int n_in,
                              void* d_out, int out_size) {
    const float* params = (const float*)d_in[0];
    float* out = (float*)d_out;
    prep_kernel<<<PREP_BLOCKS, 128>>>(params);
    dim3 grid(NSEG, NB);
    synth_kernel<<<grid, 64>>>(params, out);
}